// round 2
// baseline (speedup 1.0000x reference)
#include <cuda_runtime.h>

#define BB 8
#define N1V 50176
#define N2V 12544
#define N3V 3136
#define CNT 100352          // BB*N2V
#define BN_EPS 1e-5f

// ---------------- scratch (static device globals; no allocation) ----------------
__device__ float d_xt1[N1V * 24];       // x transposed: [n1][b*3+c]
__device__ float d_A1[N2V * 81];        // mlp(off1): [n][k*9+t]
__device__ float d_A2[N2V * 81];        // mlp(off2)
__device__ float d_y1[N2V * 256];       // layer1 out / bn-relu in place: [n][b*32+o]
__device__ float d_y2[N2V * 256];
__device__ float d_y3[N2V * 512];       // [n][b*64+o]
__device__ float d_stats[256];          // s1[32] q1[32] s2[32] q2[32] s3[64] q3[64]

// ---------------- zero stats ----------------
__global__ void k_zero(float* s) { s[threadIdx.x] = 0.f; }

// ---------------- transpose x (8,3,N1) -> xt1[n][24] ----------------
__global__ void k_transpose(const float* __restrict__ x, float* __restrict__ xt) {
    int n = blockIdx.x * 256 + threadIdx.x;
    if (n >= N1V) return;
    float4 t4[6];
    float* t = (float*)t4;
#pragma unroll
    for (int bc = 0; bc < 24; ++bc) t[bc] = x[bc * N1V + n];
    float4* dst = (float4*)(xt + n * 24);
#pragma unroll
    for (int i = 0; i < 6; ++i) dst[i] = t4[i];
}

// ---------------- weight MLP: off (N2,9,2) -> A (N2,81) ----------------
__global__ void k_mlp(const float* __restrict__ off,
                      const float* __restrict__ Wh, const float* __restrict__ bh,
                      const float* __restrict__ Wo, const float* __restrict__ bo,
                      float* __restrict__ A) {
    __shared__ float sWh[64], sbh[32], sWo[288], sbo[9];
    int tid = threadIdx.x;
    if (tid < 64) sWh[tid] = Wh[tid];
    if (tid < 32) sbh[tid] = bh[tid];
    for (int e = tid; e < 288; e += 256) sWo[e] = Wo[e];
    if (tid < 9) sbo[tid] = bo[tid];
    __syncthreads();
    int id = blockIdx.x * 256 + tid;
    if (id >= N2V * 9) return;
    float o0 = off[id * 2 + 0], o1 = off[id * 2 + 1];
    float h[32];
#pragma unroll
    for (int j = 0; j < 32; ++j)
        h[j] = fmaxf(0.f, fmaf(o0, sWh[j], fmaf(o1, sWh[32 + j], sbh[j])));
#pragma unroll
    for (int t = 0; t < 9; ++t) {
        float acc = sbo[t];
#pragma unroll
        for (int j = 0; j < 32; ++j) acc = fmaf(h[j], sWo[j * 9 + t], acc);
        A[id * 9 + t] = acc;
    }
}

// ---------------- fused interp-conv layer ----------------
// xin: [Npts_in][BB*C]   A: [N2][81]   nbr: [N2][9]
// Wg:  [O][C][9] (row-major)   bias: [O]
// yout: [N2][BB*O]  (raw, pre-BN)   gSum/gSq: [O] atomically accumulated
template <int C, int O, int OT>
__global__ void __launch_bounds__(256) k_layer(
    const float* __restrict__ xin, const float* __restrict__ A,
    const int* __restrict__ nbr, const float* __restrict__ Wg,
    const float* __restrict__ bias, float* __restrict__ yout,
    float* __restrict__ gSum, float* __restrict__ gSq)
{
    constexpr int BCin = BB * C;
    constexpr int CT = C * 9;
    constexpr int GS = (CT % 2) ? (CT + 1) : ((CT % 32 == 0) ? CT + 4 : CT);
    constexpr int NG = N2V / 4;

    extern __shared__ float sm[];
    float* sm_xg = sm;                       // 36*BCin
    float* sm_G  = sm_xg + 36 * BCin;        // 32*GS   ([pt*8+b]*GS + ct)
    float* sm_Wt = sm_G + 32 * GS;           // CT*O    ([ct*O + o])
    float* sm_a  = sm_Wt + CT * O;           // 4*81
    float* sm_bias = sm_a + 324;             // O
    float* sm_sum  = sm_bias + O;            // O
    float* sm_sq   = sm_sum + O;             // O
    int*   sm_idx  = (int*)(sm_sq + O);      // 36

    int tid = threadIdx.x;

    // one-time per CTA: weight transpose, bias, zero stats
    for (int e = tid; e < CT * O; e += 256) {
        int ct = e / O, o = e % O;
        sm_Wt[e] = Wg[o * CT + ct];
    }
    for (int e = tid; e < O; e += 256) { sm_bias[e] = bias[e]; sm_sum[e] = 0.f; sm_sq[e] = 0.f; }
    __syncthreads();

    const int pt_c = tid >> 6;          // 0..3
    const int r    = tid & 63;
    const int b_c  = r >> 3;            // 0..7
    const int og   = r & 7;             // 0..7

    float ssum[OT], ssq[OT];
#pragma unroll
    for (int j = 0; j < OT; ++j) { ssum[j] = 0.f; ssq[j] = 0.f; }

    for (int g = blockIdx.x; g < NG; g += gridDim.x) {
        int n0 = g * 4;
        if (tid < 36) sm_idx[tid] = nbr[n0 * 9 + tid];
        for (int e = tid; e < 324; e += 256) sm_a[e] = A[n0 * 81 + e];
        __syncthreads();

        // gather 4 pts x 9 rows of BCin floats
        constexpr int GEL = 36 * BCin;
        for (int e = tid; e < GEL; e += 256) {
            int pk = e / BCin;
            int bc = e - pk * BCin;
            sm_xg[e] = xin[(size_t)sm_idx[pk] * BCin + bc];
        }
        __syncthreads();

        // stage B: G[pt][b][c*9+t] = sum_k xg[pt][k][b*C+c] * a[pt][k*9+t]
        if (C == 32) {
            int bB = tid >> 5, cB = tid & 31;
#pragma unroll
            for (int pt = 0; pt < 4; ++pt) {
                float xr[9];
#pragma unroll
                for (int k = 0; k < 9; ++k) xr[k] = sm_xg[(pt * 9 + k) * BCin + tid];
                const float* ap = sm_a + pt * 81;
                float* gp = sm_G + (pt * 8 + bB) * GS + cB * 9;
#pragma unroll
                for (int t = 0; t < 9; ++t) {
                    float acc = 0.f;
#pragma unroll
                    for (int k = 0; k < 9; ++k) acc = fmaf(xr[k], ap[k * 9 + t], acc);
                    gp[t] = acc;
                }
            }
        } else {  // C == 3
            if (tid < 96) {
                int ptB = tid / 24, bc = tid % 24, bB = bc / 3, cB = bc % 3;
                float xr[9];
#pragma unroll
                for (int k = 0; k < 9; ++k) xr[k] = sm_xg[(ptB * 9 + k) * BCin + bc];
                const float* ap = sm_a + ptB * 81;
                float* gp = sm_G + (ptB * 8 + bB) * GS + cB * 9;
#pragma unroll
                for (int t = 0; t < 9; ++t) {
                    float acc = 0.f;
#pragma unroll
                    for (int k = 0; k < 9; ++k) acc = fmaf(xr[k], ap[k * 9 + t], acc);
                    gp[t] = acc;
                }
            }
        }
        __syncthreads();

        // stage C: y[b][o] = bias[o] + sum_ct G[b][ct] * Wt[ct][o]
        {
            const float* Gp = sm_G + (pt_c * 8 + b_c) * GS;
            const float* Wp = sm_Wt + og * OT;
            float acc[OT];
#pragma unroll
            for (int j = 0; j < OT; ++j) acc[j] = sm_bias[og * OT + j];
#pragma unroll 9
            for (int ct = 0; ct < CT; ++ct) {
                float gv = Gp[ct];
#pragma unroll
                for (int j = 0; j < OT; ++j) acc[j] = fmaf(gv, Wp[ct * O + j], acc[j]);
            }
            float* yp = yout + (size_t)(n0 + pt_c) * (BB * O) + b_c * O + og * OT;
#pragma unroll
            for (int j = 0; j < OT; ++j) {
                yp[j] = acc[j];
                ssum[j] += acc[j];
                ssq[j] = fmaf(acc[j], acc[j], ssq[j]);
            }
        }
        __syncthreads();
    }

    // stats reduction: regs -> smem -> global
#pragma unroll
    for (int j = 0; j < OT; ++j) {
        atomicAdd(sm_sum + og * OT + j, ssum[j]);
        atomicAdd(sm_sq  + og * OT + j, ssq[j]);
    }
    __syncthreads();
    for (int e = tid; e < O; e += 256) {
        atomicAdd(gSum + e, sm_sum[e]);
        atomicAdd(gSq + e, sm_sq[e]);
    }
}

// ---------------- BN + ReLU in place ----------------
template <int O>
__global__ void k_bnrelu(float* __restrict__ y,
                         const float* __restrict__ gS, const float* __restrict__ gQ,
                         const float* __restrict__ gamma, const float* __restrict__ beta,
                         int total4) {
    int i = blockIdx.x * 256 + threadIdx.x;
    if (i >= total4) return;
    float4 v = ((float4*)y)[i];
    int o0 = (i * 4) & (O - 1);
    float r[4] = {v.x, v.y, v.z, v.w};
#pragma unroll
    for (int j = 0; j < 4; ++j) {
        int o = o0 + j;
        float mean = gS[o] * (1.f / CNT);
        float var = gQ[o] * (1.f / CNT) - mean * mean;
        float sc = gamma[o] * rsqrtf(var + BN_EPS);
        float sh = beta[o] - mean * sc;
        r[j] = fmaxf(0.f, fmaf(r[j], sc, sh));
    }
    ((float4*)y)[i] = make_float4(r[0], r[1], r[2], r[3]);
}

// ---------------- max pool + transpose to (8,64,N3) ----------------
__global__ void k_pool(const float* __restrict__ x3, const int* __restrict__ pidx,
                       float* __restrict__ out) {
    __shared__ float smp[16 * 513];
    int tid = threadIdx.x;
    int base = blockIdx.x * 16;
    for (int i = 0; i < 16; ++i) {
        int n3 = base + i;
        float m0 = -3.4e38f, m1 = -3.4e38f;
#pragma unroll
        for (int k = 0; k < 9; ++k) {
            const float* row = x3 + (size_t)pidx[n3 * 9 + k] * 512;
            m0 = fmaxf(m0, row[tid]);
            m1 = fmaxf(m1, row[tid + 256]);
        }
        smp[i * 513 + tid] = m0;
        smp[i * 513 + tid + 256] = m1;
    }
    __syncthreads();
#pragma unroll
    for (int h = 0; h < 2; ++h) {
        int bc = tid + h * 256;
        float4 t4[4];
        float* t = (float*)t4;
#pragma unroll
        for (int i = 0; i < 16; ++i) t[i] = smp[i * 513 + bc];
        float4* dst = (float4*)(out + (size_t)bc * N3V + base);
#pragma unroll
        for (int q = 0; q < 4; ++q) dst[q] = t4[q];
    }
}

// ---------------- smem size helper ----------------
static constexpr size_t layer_smem(int C, int O) {
    int CT = C * 9;
    int GS = (CT % 2) ? (CT + 1) : ((CT % 32 == 0) ? CT + 4 : CT);
    return (size_t)(36 * (8 * C) + 32 * GS + CT * O + 324 + 3 * O + 36) * 4;
}

extern "C" void kernel_launch(void* const* d_in, const int* in_sizes, int n_in,
                              void* d_out, int out_size) {
    const float* x    = (const float*)d_in[0];
    const int*   nbr1 = (const int*)d_in[1];
    const float* off1 = (const float*)d_in[2];
    const int*   nbr2 = (const int*)d_in[3];
    const float* off2 = (const float*)d_in[4];
    const int*   pidx = (const int*)d_in[5];
    const float* Wh   = (const float*)d_in[6];
    const float* bh   = (const float*)d_in[7];
    const float* Wo   = (const float*)d_in[8];
    const float* bo   = (const float*)d_in[9];
    const float* W1   = (const float*)d_in[10];
    const float* b1   = (const float*)d_in[11];
    const float* W2   = (const float*)d_in[12];
    const float* b2   = (const float*)d_in[13];
    const float* W3   = (const float*)d_in[14];
    const float* b3   = (const float*)d_in[15];
    const float* g1   = (const float*)d_in[16];
    const float* be1  = (const float*)d_in[17];
    const float* g2   = (const float*)d_in[18];
    const float* be2  = (const float*)d_in[19];
    const float* g3   = (const float*)d_in[20];
    const float* be3  = (const float*)d_in[21];
    float* out = (float*)d_out;

    float *xt1, *A1, *A2, *y1, *y2, *y3, *stats;
    cudaGetSymbolAddress((void**)&xt1, d_xt1);
    cudaGetSymbolAddress((void**)&A1, d_A1);
    cudaGetSymbolAddress((void**)&A2, d_A2);
    cudaGetSymbolAddress((void**)&y1, d_y1);
    cudaGetSymbolAddress((void**)&y2, d_y2);
    cudaGetSymbolAddress((void**)&y3, d_y3);
    cudaGetSymbolAddress((void**)&stats, d_stats);

    size_t sm1 = layer_smem(3, 32);
    size_t sm2 = layer_smem(32, 32);
    size_t sm3 = layer_smem(32, 64);
    cudaFuncSetAttribute(k_layer<32, 32, 4>, cudaFuncAttributeMaxDynamicSharedMemorySize, (int)sm2);
    cudaFuncSetAttribute(k_layer<32, 64, 8>, cudaFuncAttributeMaxDynamicSharedMemorySize, (int)sm3);

    k_zero<<<1, 256>>>(stats);
    k_transpose<<<(N1V + 255) / 256, 256>>>(x, xt1);
    k_mlp<<<(N2V * 9 + 255) / 256, 256>>>(off1, Wh, bh, Wo, bo, A1);
    k_mlp<<<(N2V * 9 + 255) / 256, 256>>>(off2, Wh, bh, Wo, bo, A2);

    k_layer<3, 32, 4><<<592, 256, sm1>>>(xt1, A1, nbr1, W1, b1, y1, stats + 0, stats + 32);
    k_bnrelu<32><<<(N2V * 256 / 4 + 255) / 256, 256>>>(y1, stats + 0, stats + 32, g1, be1, N2V * 256 / 4);

    k_layer<32, 32, 4><<<296, 256, sm2>>>(y1, A2, nbr2, W2, b2, y2, stats + 64, stats + 96);
    k_bnrelu<32><<<(N2V * 256 / 4 + 255) / 256, 256>>>(y2, stats + 64, stats + 96, g2, be2, N2V * 256 / 4);

    k_layer<32, 64, 8><<<148, 256, sm3>>>(y2, A2, nbr2, W3, b3, y3, stats + 128, stats + 192);
    k_bnrelu<64><<<(N2V * 512 / 4 + 255) / 256, 256>>>(y3, stats + 128, stats + 192, g3, be3, N2V * 512 / 4);

    k_pool<<<N3V / 16, 256>>>(y3, pidx, out);
}

// round 3
// speedup vs baseline: 2.2414x; 2.2414x over previous
#include <cuda_runtime.h>

#define BB 8
#define N1V 50176
#define N2V 12544
#define N3V 3136
#define CNT 100352          // BB*N2V
#define BN_EPS 1e-5f

typedef unsigned long long ull;

// ---------------- scratch (static device globals; no allocation) ----------------
__device__ float d_xt1[N1V * 24];       // x transposed: [n1][b*3+c]
__device__ float d_A1[N2V * 81];        // mlp(off1): [n][k*9+t]
__device__ float d_A2[N2V * 81];        // mlp(off2)
__device__ float d_y1[N2V * 256];       // layer1 out: [n][b*32+o]
__device__ float d_y2[N2V * 256];
__device__ float d_y3[N2V * 512];       // [n][b*64+o]
__device__ float d_stats[256];

// ---------------- f32x2 helpers ----------------
__device__ __forceinline__ ull pack2(float lo, float hi) {
    ull r; asm("mov.b64 %0, {%1, %2};" : "=l"(r) : "f"(lo), "f"(hi)); return r;
}
__device__ __forceinline__ void unpack2(ull v, float& lo, float& hi) {
    asm("mov.b64 {%0, %1}, %2;" : "=f"(lo), "=f"(hi) : "l"(v));
}
__device__ __forceinline__ ull ffma2(ull a, ull b, ull c) {
    ull d; asm("fma.rn.f32x2 %0, %1, %2, %3;" : "=l"(d) : "l"(a), "l"(b), "l"(c)); return d;
}

// ---------------- zero stats ----------------
__global__ void k_zero(float* s) { s[threadIdx.x] = 0.f; }

// ---------------- transpose x (8,3,N1) -> xt1[n][24] ----------------
__global__ void k_transpose(const float* __restrict__ x, float* __restrict__ xt) {
    int n = blockIdx.x * 256 + threadIdx.x;
    if (n >= N1V) return;
    float4 t4[6];
    float* t = (float*)t4;
#pragma unroll
    for (int bc = 0; bc < 24; ++bc) t[bc] = x[bc * N1V + n];
    float4* dst = (float4*)(xt + n * 24);
#pragma unroll
    for (int i = 0; i < 6; ++i) dst[i] = t4[i];
}

// ---------------- weight MLP: off (N2,9,2) -> A (N2,81) ----------------
__global__ void __launch_bounds__(128) k_mlp(const float* __restrict__ off,
                      const float* __restrict__ Wh, const float* __restrict__ bh,
                      const float* __restrict__ Wo, const float* __restrict__ bo,
                      float* __restrict__ A) {
    __shared__ float sWh[64], sbh[32], sWo[288], sbo[9];
    int tid = threadIdx.x;
    if (tid < 64) sWh[tid] = Wh[tid];
    if (tid < 32) sbh[tid] = bh[tid];
    for (int e = tid; e < 288; e += 128) sWo[e] = Wo[e];
    if (tid < 9) sbo[tid] = bo[tid];
    __syncthreads();
    int id = blockIdx.x * 128 + tid;
    if (id >= N2V * 9) return;
    float2 o2 = ((const float2*)off)[id];
    float h[32];
#pragma unroll
    for (int j = 0; j < 32; ++j)
        h[j] = fmaxf(0.f, fmaf(o2.x, sWh[j], fmaf(o2.y, sWh[32 + j], sbh[j])));
#pragma unroll
    for (int t = 0; t < 9; ++t) {
        float acc = sbo[t];
#pragma unroll
        for (int j = 0; j < 32; ++j) acc = fmaf(h[j], sWo[j * 9 + t], acc);
        A[id * 9 + t] = acc;
    }
}

// ---------------- fused interp-conv layer ----------------
// xin: [Npts_in][BB*C]  A: [N2][81]  nbr: [N2][9]  Wg: [O][C*9]  bias: [O]
// yout: [N2][BB*O]  gSum/gSq: [O]
// Group of P=16 points -> 128 GEMM rows. Stage B gathers from global directly.
template <int C, int O, int OT, int GS>
__global__ void __launch_bounds__(256) k_layer(
    const float* __restrict__ xin, const float* __restrict__ A,
    const int* __restrict__ nbr, const float* __restrict__ Wg,
    const float* __restrict__ bias, float* __restrict__ yout,
    float* __restrict__ gSum, float* __restrict__ gSq)
{
    constexpr int BCin = BB * C;
    constexpr int CT = C * 9;
    constexpr int P = 16;
    constexpr int ROWS = P * BB;   // 128
    constexpr int NG = N2V / P;    // 784
    constexpr int OTH = OT / 2;

    extern __shared__ float sm[];
    float* sm_Wt  = sm;                        // CT*O   [ct*O + o]
    float* sm_G   = sm_Wt + CT * O;            // ROWS*GS
    float* sm_a   = sm_G + ROWS * GS;          // P*108  [pt][k*12 + t] (padded)
    float* sm_bias= sm_a + P * 108;            // O
    float* sm_sum = sm_bias + O;               // O
    float* sm_sq  = sm_sum + O;                // O
    int*   sm_idx = (int*)(sm_sq + O);         // P*9

    int tid = threadIdx.x;

    // one-time: weight transpose, bias, zero stats
    for (int e = tid; e < CT * O; e += 256) {
        int ct = e / O, o = e - ct * O;
        sm_Wt[e] = Wg[o * CT + ct];
    }
    for (int e = tid; e < O; e += 256) { sm_bias[e] = bias[e]; sm_sum[e] = 0.f; sm_sq[e] = 0.f; }
    __syncthreads();

    const int rt   = tid >> 3;   // 0..31 (4 rows each)
    const int colt = tid & 7;    // 0..7  (OT cols each)

    float ssum[OT], ssq[OT];
#pragma unroll
    for (int j = 0; j < OT; ++j) { ssum[j] = 0.f; ssq[j] = 0.f; }

    for (int g = blockIdx.x; g < NG; g += gridDim.x) {
        int n0 = g * P;
        if (tid < P * 9) sm_idx[tid] = nbr[n0 * 9 + tid];
        for (int e = tid; e < P * 81; e += 256) {
            int pt = e / 81, r = e - pt * 81, k = r / 9, t = r - k * 9;
            sm_a[pt * 108 + k * 12 + t] = A[(size_t)n0 * 81 + e];
        }
        __syncthreads();

        // ---- stage B: G[pt*8+b][c*9+t] = sum_k xin[idx[pt][k]][b*C+c] * a[pt][k][t]
        if (C == 32) {
            int b = tid >> 5, c = tid & 31;
#pragma unroll 1
            for (int pt = 0; pt < P; ++pt) {
                const float* ap = sm_a + pt * 108;
                const int* ip = sm_idx + pt * 9;
                ull ac01 = 0, ac23 = 0, ac45 = 0, ac67 = 0; float ac8 = 0.f;
#pragma unroll
                for (int k = 0; k < 9; ++k) {
                    float xk = xin[(size_t)ip[k] * BCin + tid];
                    ull xx = pack2(xk, xk);
                    const ulonglong2* a2 = (const ulonglong2*)(ap + k * 12);
                    ulonglong2 a03 = a2[0], a47 = a2[1];
                    float a8 = ap[k * 12 + 8];
                    ac01 = ffma2(xx, a03.x, ac01);
                    ac23 = ffma2(xx, a03.y, ac23);
                    ac45 = ffma2(xx, a47.x, ac45);
                    ac67 = ffma2(xx, a47.y, ac67);
                    ac8 = fmaf(xk, a8, ac8);
                }
                float* gp = sm_G + (pt * 8 + b) * GS + c * 9;
                unpack2(ac01, gp[0], gp[1]);
                unpack2(ac23, gp[2], gp[3]);
                unpack2(ac45, gp[4], gp[5]);
                unpack2(ac67, gp[6], gp[7]);
                gp[8] = ac8;
            }
        } else {  // C == 3
            for (int it = tid; it < P * 24; it += 256) {
                int pt = it / 24, bc = it - pt * 24;
                int b = bc / 3, c = bc - b * 3;
                const float* ap = sm_a + pt * 108;
                const int* ip = sm_idx + pt * 9;
                ull ac01 = 0, ac23 = 0, ac45 = 0, ac67 = 0; float ac8 = 0.f;
#pragma unroll
                for (int k = 0; k < 9; ++k) {
                    float xk = xin[(size_t)ip[k] * BCin + bc];
                    ull xx = pack2(xk, xk);
                    const ulonglong2* a2 = (const ulonglong2*)(ap + k * 12);
                    ulonglong2 a03 = a2[0], a47 = a2[1];
                    float a8 = ap[k * 12 + 8];
                    ac01 = ffma2(xx, a03.x, ac01);
                    ac23 = ffma2(xx, a03.y, ac23);
                    ac45 = ffma2(xx, a47.x, ac45);
                    ac67 = ffma2(xx, a47.y, ac67);
                    ac8 = fmaf(xk, a8, ac8);
                }
                float* gp = sm_G + (pt * 8 + b) * GS + c * 9;
                unpack2(ac01, gp[0], gp[1]);
                unpack2(ac23, gp[2], gp[3]);
                unpack2(ac45, gp[4], gp[5]);
                unpack2(ac67, gp[6], gp[7]);
                gp[8] = ac8;
            }
        }
        __syncthreads();

        // ---- stage C: y[row][o] = bias[o] + sum_ct G[row][ct] * Wt[ct][o]
        {
            const float* Gp = sm_G + (rt * 4) * GS;
            ull bini[OTH];
#pragma unroll
            for (int j2 = 0; j2 < OTH; ++j2)
                bini[j2] = pack2(sm_bias[colt * OT + 2 * j2], sm_bias[colt * OT + 2 * j2 + 1]);
            ull acc[4][OTH];
#pragma unroll
            for (int i = 0; i < 4; ++i)
#pragma unroll
                for (int j2 = 0; j2 < OTH; ++j2) acc[i][j2] = bini[j2];

#pragma unroll 4
            for (int ct = 0; ct < CT; ++ct) {
                ull w[OTH];
                if (OT == 8) {
                    const ulonglong2* wp = (const ulonglong2*)(sm_Wt + ct * O + colt * 8);
                    ulonglong2 wA = wp[0], wB = wp[1];
                    w[0] = wA.x; w[1] = wA.y;
                    if (OTH > 2) { w[2] = wB.x; w[3] = wB.y; }
                } else {
                    ulonglong2 wA = *(const ulonglong2*)(sm_Wt + ct * O + colt * 4);
                    w[0] = wA.x; w[1] = wA.y;
                }
#pragma unroll
                for (int i = 0; i < 4; ++i) {
                    float gv = Gp[i * GS + ct];
                    ull gg = pack2(gv, gv);
#pragma unroll
                    for (int j2 = 0; j2 < OTH; ++j2)
                        acc[i][j2] = ffma2(gg, w[j2], acc[i][j2]);
                }
            }

#pragma unroll
            for (int i = 0; i < 4; ++i) {
                int row = rt * 4 + i, pt = row >> 3, b = row & 7;
                float* yp = yout + (size_t)(n0 + pt) * (BB * O) + b * O + colt * OT;
#pragma unroll
                for (int j2 = 0; j2 < OTH; ++j2) {
                    float lo, hi;
                    unpack2(acc[i][j2], lo, hi);
                    yp[2 * j2] = lo; yp[2 * j2 + 1] = hi;
                    ssum[2 * j2] += lo; ssum[2 * j2 + 1] += hi;
                    ssq[2 * j2] = fmaf(lo, lo, ssq[2 * j2]);
                    ssq[2 * j2 + 1] = fmaf(hi, hi, ssq[2 * j2 + 1]);
                }
            }
        }
        __syncthreads();
    }

    // stats: regs -> smem -> global
#pragma unroll
    for (int j = 0; j < OT; ++j) {
        atomicAdd(sm_sum + colt * OT + j, ssum[j]);
        atomicAdd(sm_sq  + colt * OT + j, ssq[j]);
    }
    __syncthreads();
    for (int e = tid; e < O; e += 256) {
        atomicAdd(gSum + e, sm_sum[e]);
        atomicAdd(gSq + e, sm_sq[e]);
    }
}

// ---------------- BN + ReLU in place ----------------
template <int O>
__global__ void k_bnrelu(float* __restrict__ y,
                         const float* __restrict__ gS, const float* __restrict__ gQ,
                         const float* __restrict__ gamma, const float* __restrict__ beta,
                         int total4) {
    int i = blockIdx.x * 256 + threadIdx.x;
    if (i >= total4) return;
    float4 v = ((float4*)y)[i];
    int o0 = (i * 4) & (O - 1);
    float r[4] = {v.x, v.y, v.z, v.w};
#pragma unroll
    for (int j = 0; j < 4; ++j) {
        int o = o0 + j;
        float mean = gS[o] * (1.f / CNT);
        float var = gQ[o] * (1.f / CNT) - mean * mean;
        float sc = gamma[o] * rsqrtf(var + BN_EPS);
        float sh = beta[o] - mean * sc;
        r[j] = fmaxf(0.f, fmaf(r[j], sc, sh));
    }
    ((float4*)y)[i] = make_float4(r[0], r[1], r[2], r[3]);
}

// ---------------- max pool + transpose to (8,64,N3) ----------------
__global__ void k_pool(const float* __restrict__ x3, const int* __restrict__ pidx,
                       float* __restrict__ out) {
    __shared__ float smp[16 * 513];
    int tid = threadIdx.x;
    int base = blockIdx.x * 16;
    for (int i = 0; i < 16; ++i) {
        int n3 = base + i;
        float m0 = -3.4e38f, m1 = -3.4e38f;
#pragma unroll
        for (int k = 0; k < 9; ++k) {
            const float* row = x3 + (size_t)pidx[n3 * 9 + k] * 512;
            m0 = fmaxf(m0, row[tid]);
            m1 = fmaxf(m1, row[tid + 256]);
        }
        smp[i * 513 + tid] = m0;
        smp[i * 513 + tid + 256] = m1;
    }
    __syncthreads();
#pragma unroll
    for (int h = 0; h < 2; ++h) {
        int bc = tid + h * 256;
        float4 t4[4];
        float* t = (float*)t4;
#pragma unroll
        for (int i = 0; i < 16; ++i) t[i] = smp[i * 513 + bc];
        float4* dst = (float4*)(out + (size_t)bc * N3V + base);
#pragma unroll
        for (int q = 0; q < 4; ++q) dst[q] = t4[q];
    }
}

// ---------------- smem size ----------------
static constexpr size_t layer_smem(int C, int O, int GS) {
    return (size_t)4 * (C * 9 * O + 128 * GS + 16 * 108 + 3 * O + 144);
}

extern "C" void kernel_launch(void* const* d_in, const int* in_sizes, int n_in,
                              void* d_out, int out_size) {
    const float* x    = (const float*)d_in[0];
    const int*   nbr1 = (const int*)d_in[1];
    const float* off1 = (const float*)d_in[2];
    const int*   nbr2 = (const int*)d_in[3];
    const float* off2 = (const float*)d_in[4];
    const int*   pidx = (const int*)d_in[5];
    const float* Wh   = (const float*)d_in[6];
    const float* bh   = (const float*)d_in[7];
    const float* Wo   = (const float*)d_in[8];
    const float* bo   = (const float*)d_in[9];
    const float* W1   = (const float*)d_in[10];
    const float* b1   = (const float*)d_in[11];
    const float* W2   = (const float*)d_in[12];
    const float* b2   = (const float*)d_in[13];
    const float* W3   = (const float*)d_in[14];
    const float* b3   = (const float*)d_in[15];
    const float* g1   = (const float*)d_in[16];
    const float* be1  = (const float*)d_in[17];
    const float* g2   = (const float*)d_in[18];
    const float* be2  = (const float*)d_in[19];
    const float* g3   = (const float*)d_in[20];
    const float* be3  = (const float*)d_in[21];
    float* out = (float*)d_out;

    float *xt1, *A1, *A2, *y1, *y2, *y3, *stats;
    cudaGetSymbolAddress((void**)&xt1, d_xt1);
    cudaGetSymbolAddress((void**)&A1, d_A1);
    cudaGetSymbolAddress((void**)&A2, d_A2);
    cudaGetSymbolAddress((void**)&y1, d_y1);
    cudaGetSymbolAddress((void**)&y2, d_y2);
    cudaGetSymbolAddress((void**)&y3, d_y3);
    cudaGetSymbolAddress((void**)&stats, d_stats);

    const size_t sm1 = layer_smem(3, 32, 29);
    const size_t sm2 = layer_smem(32, 32, 289);
    const size_t sm3 = layer_smem(32, 64, 289);
    cudaFuncSetAttribute(k_layer<3, 32, 4, 29>,   cudaFuncAttributeMaxDynamicSharedMemorySize, (int)sm1);
    cudaFuncSetAttribute(k_layer<32, 32, 4, 289>, cudaFuncAttributeMaxDynamicSharedMemorySize, (int)sm2);
    cudaFuncSetAttribute(k_layer<32, 64, 8, 289>, cudaFuncAttributeMaxDynamicSharedMemorySize, (int)sm3);

    k_zero<<<1, 256>>>(stats);
    k_transpose<<<(N1V + 255) / 256, 256>>>(x, xt1);
    k_mlp<<<(N2V * 9 + 127) / 128, 128>>>(off1, Wh, bh, Wo, bo, A1);
    k_mlp<<<(N2V * 9 + 127) / 128, 128>>>(off2, Wh, bh, Wo, bo, A2);

    k_layer<3, 32, 4, 29><<<148, 256, sm1>>>(xt1, A1, nbr1, W1, b1, y1, stats + 0, stats + 32);
    k_bnrelu<32><<<(N2V * 256 / 4 + 255) / 256, 256>>>(y1, stats + 0, stats + 32, g1, be1, N2V * 256 / 4);

    k_layer<32, 32, 4, 289><<<148, 256, sm2>>>(y1, A2, nbr2, W2, b2, y2, stats + 64, stats + 96);
    k_bnrelu<32><<<(N2V * 256 / 4 + 255) / 256, 256>>>(y2, stats + 64, stats + 96, g2, be2, N2V * 256 / 4);

    k_layer<32, 64, 8, 289><<<148, 256, sm3>>>(y2, A2, nbr2, W3, b3, y3, stats + 128, stats + 192);
    k_bnrelu<64><<<(N2V * 512 / 4 + 255) / 256, 256>>>(y3, stats + 128, stats + 192, g3, be3, N2V * 512 / 4);

    k_pool<<<N3V / 16, 256>>>(y3, pidx, out);
}